// round 1
// baseline (speedup 1.0000x reference)
#include <cuda_runtime.h>

// Elman RNN: h_t = tanh(x_t*Whx + h_{t-1}@Whh + bh), t=0..1023; out = h@Wph + bp
// B=4096, T=1024, H=64, C=10, input_dim=1.
// Strategy: packed f32x2 FMA (Blackwell dual-issue fp32), thread = (row-pair, col).

#define T_LEN 1024
#define H 64
#define NC 10
#define PAIRS 2              // row-pairs per block
#define ROWS (2*PAIRS)       // 4 rows per block
#define NTHREADS (PAIRS*H)   // 128 threads

__device__ __forceinline__ unsigned long long pk2(float a, float b){
    unsigned long long r;
    asm("mov.b64 %0, {%1, %2};" : "=l"(r) : "f"(a), "f"(b));
    return r;
}
__device__ __forceinline__ void upk2(unsigned long long v, float &a, float &b){
    asm("mov.b64 {%0, %1}, %2;" : "=f"(a), "=f"(b) : "l"(v));
}
__device__ __forceinline__ unsigned long long fma2(unsigned long long a,
                                                   unsigned long long b,
                                                   unsigned long long c){
    unsigned long long d;
    asm("fma.rn.f32x2 %0, %1, %2, %3;" : "=l"(d) : "l"(a), "l"(b), "l"(c));
    return d;
}
__device__ __forceinline__ unsigned long long add2(unsigned long long a,
                                                   unsigned long long b){
    unsigned long long d;
    asm("add.rn.f32x2 %0, %1, %2;" : "=l"(d) : "l"(a), "l"(b));
    return d;
}
// tanh via exp: (e^{2v}-1)/(e^{2v}+1). __expf ~2ulp; cancellation analysis:
// for tiny v, e-1 carries abs err ~ulp(1) -> rel err ~6e-5 at v=1e-3. Fine vs 1e-3.
__device__ __forceinline__ float ftanh(float v){
    float e = __expf(2.0f * v);
    return __fdividef(e - 1.0f, e + 1.0f);
}

__global__ void __launch_bounds__(NTHREADS)
rnn_kernel(const float* __restrict__ x,      // [4096,1024]
           const float* __restrict__ Whx,    // [1,64]
           const float* __restrict__ Whh,    // [64,64]
           const float* __restrict__ Wph,    // [64,10]
           const float* __restrict__ bh,     // [1,64]
           const float* __restrict__ bp,     // [1,10]
           float* __restrict__ out)          // [4096,10]
{
    // h double-buffered, row-pair interleaved: hsh[buf][pair][j][0/1] = h of row (2p)/(2p+1)
    __shared__ __align__(16) float hsh[2][PAIRS][H][2];

    const int tid = threadIdx.x;
    const int c   = tid & (H - 1);   // column 0..63
    const int p   = tid >> 6;        // row-pair 0..PAIRS-1
    const int rowBase = blockIdx.x * ROWS;
    const int r0 = rowBase + 2 * p;

    const float whxc = Whx[c];
    const float bhc  = bh[c];

    // Whh column c, duplicated into packed 64-bit regs: w2[j] = {Whh[j][c], Whh[j][c]}
    unsigned long long w2[H];
#pragma unroll
    for (int j = 0; j < H; j++){
        float w = Whh[j * H + c];
        w2[j] = pk2(w, w);
    }

    // h0 = 0 (each thread zeroes its (p, j=c) slot; c spans 0..63 -> full coverage)
    hsh[0][p][c][0] = 0.0f;
    hsh[0][p][c][1] = 0.0f;
    __syncthreads();

    const float* xr0 = x + (size_t)r0 * T_LEN;
    const float* xr1 = xr0 + T_LEN;

    int buf = 0;
    for (int t = 0; t < T_LEN; t++){
        // input projection for both rows of the pair (LDG broadcast, L1-hot)
        float xv0 = __ldg(xr0 + t) * whxc + bhc;
        float xv1 = __ldg(xr1 + t) * whxc + bhc;

        unsigned long long a0 = pk2(xv0, xv1);
        unsigned long long a1 = 0ull, a2 = 0ull, a3 = 0ull;

        // hp[i] = 16B = {h0[2i], h1[2i], h0[2i+1], h1[2i+1]} -> two packed operands
        const ulonglong2* hp = (const ulonglong2*)&hsh[buf][p][0][0];
#pragma unroll
        for (int i = 0; i < H / 2; i += 2){        // i = 0,2,...,30 : 16 iters, 64 fma2
            ulonglong2 v = hp[i];
            ulonglong2 u = hp[i + 1];
            a0 = fma2(v.x, w2[2 * i],     a0);
            a1 = fma2(v.y, w2[2 * i + 1], a1);
            a2 = fma2(u.x, w2[2 * i + 2], a2);
            a3 = fma2(u.y, w2[2 * i + 3], a3);
        }
        unsigned long long s = add2(add2(a0, a1), add2(a2, a3));
        float s0, s1;
        upk2(s, s0, s1);

        float h0 = ftanh(s0);
        float h1 = ftanh(s1);

        int nb = buf ^ 1;
        *(float2*)&hsh[nb][p][c][0] = make_float2(h0, h1);
        __syncthreads();
        buf = nb;
    }

    // Final projection: p = h_final @ Wph + bp  (h_final lives in hsh[buf])
    if (tid < ROWS * NC){
        int r = tid / NC;
        int k = tid % NC;
        float acc = bp[k];
#pragma unroll
        for (int j = 0; j < H; j++)
            acc += hsh[buf][r >> 1][j][r & 1] * __ldg(Wph + j * NC + k);
        out[(size_t)(rowBase + r) * NC + k] = acc;
    }
}

extern "C" void kernel_launch(void* const* d_in, const int* in_sizes, int n_in,
                              void* d_out, int out_size) {
    const float* x   = (const float*)d_in[0];
    const float* Whx = (const float*)d_in[1];
    const float* Whh = (const float*)d_in[2];
    const float* Wph = (const float*)d_in[3];
    const float* bh  = (const float*)d_in[4];
    const float* bp  = (const float*)d_in[5];
    float* out = (float*)d_out;

    rnn_kernel<<<4096 / ROWS, NTHREADS>>>(x, Whx, Whh, Wph, bh, bp, out);
}

// round 2
// speedup vs baseline: 1.0538x; 1.0538x over previous
#include <cuda_runtime.h>

// Elman RNN: h_t = tanh(x_t*Whx + h_{t-1}@Whh + bh), t=0..1023; out = h@Wph + bp
// B=4096, T=1024, H=64, C=10, input_dim=1.
// Strategy: packed f32x2 FMA (Blackwell dual-issue fp32), thread = (row-pair, col).

#define T_LEN 1024
#define H 64
#define NC 10
#define PAIRS 2              // row-pairs per block
#define ROWS (2*PAIRS)       // 4 rows per block
#define NTHREADS (PAIRS*H)   // 128 threads

__device__ __forceinline__ unsigned long long pk2(float a, float b){
    unsigned long long r;
    asm("mov.b64 %0, {%1, %2};" : "=l"(r) : "f"(a), "f"(b));
    return r;
}
__device__ __forceinline__ void upk2(unsigned long long v, float &a, float &b){
    asm("mov.b64 {%0, %1}, %2;" : "=f"(a), "=f"(b) : "l"(v));
}
__device__ __forceinline__ unsigned long long fma2(unsigned long long a,
                                                   unsigned long long b,
                                                   unsigned long long c){
    unsigned long long d;
    asm("fma.rn.f32x2 %0, %1, %2, %3;" : "=l"(d) : "l"(a), "l"(b), "l"(c));
    return d;
}
__device__ __forceinline__ unsigned long long add2(unsigned long long a,
                                                   unsigned long long b){
    unsigned long long d;
    asm("add.rn.f32x2 %0, %1, %2;" : "=l"(d) : "l"(a), "l"(b));
    return d;
}
// tanh via exp: (e^{2v}-1)/(e^{2v}+1). __expf ~2ulp; cancellation analysis:
// for tiny v, e-1 carries abs err ~ulp(1) -> rel err ~6e-5 at v=1e-3. Fine vs 1e-3.
__device__ __forceinline__ float ftanh(float v){
    float e = __expf(2.0f * v);
    return __fdividef(e - 1.0f, e + 1.0f);
}

__global__ void __launch_bounds__(NTHREADS)
rnn_kernel(const float* __restrict__ x,      // [4096,1024]
           const float* __restrict__ Whx,    // [1,64]
           const float* __restrict__ Whh,    // [64,64]
           const float* __restrict__ Wph,    // [64,10]
           const float* __restrict__ bh,     // [1,64]
           const float* __restrict__ bp,     // [1,10]
           float* __restrict__ out)          // [4096,10]
{
    // h double-buffered, row-pair interleaved: hsh[buf][pair][j][0/1] = h of row (2p)/(2p+1)
    __shared__ __align__(16) float hsh[2][PAIRS][H][2];

    const int tid = threadIdx.x;
    const int c   = tid & (H - 1);   // column 0..63
    const int p   = tid >> 6;        // row-pair 0..PAIRS-1
    const int rowBase = blockIdx.x * ROWS;
    const int r0 = rowBase + 2 * p;

    const float whxc = Whx[c];
    const float bhc  = bh[c];

    // Whh column c, duplicated into packed 64-bit regs: w2[j] = {Whh[j][c], Whh[j][c]}
    unsigned long long w2[H];
#pragma unroll
    for (int j = 0; j < H; j++){
        float w = Whh[j * H + c];
        w2[j] = pk2(w, w);
    }

    // h0 = 0 (each thread zeroes its (p, j=c) slot; c spans 0..63 -> full coverage)
    hsh[0][p][c][0] = 0.0f;
    hsh[0][p][c][1] = 0.0f;
    __syncthreads();

    const float* xr0 = x + (size_t)r0 * T_LEN;
    const float* xr1 = xr0 + T_LEN;

    int buf = 0;
    for (int t = 0; t < T_LEN; t++){
        // input projection for both rows of the pair (LDG broadcast, L1-hot)
        float xv0 = __ldg(xr0 + t) * whxc + bhc;
        float xv1 = __ldg(xr1 + t) * whxc + bhc;

        unsigned long long a0 = pk2(xv0, xv1);
        unsigned long long a1 = 0ull, a2 = 0ull, a3 = 0ull;

        // hp[i] = 16B = {h0[2i], h1[2i], h0[2i+1], h1[2i+1]} -> two packed operands
        const ulonglong2* hp = (const ulonglong2*)&hsh[buf][p][0][0];
#pragma unroll
        for (int i = 0; i < H / 2; i += 2){        // i = 0,2,...,30 : 16 iters, 64 fma2
            ulonglong2 v = hp[i];
            ulonglong2 u = hp[i + 1];
            a0 = fma2(v.x, w2[2 * i],     a0);
            a1 = fma2(v.y, w2[2 * i + 1], a1);
            a2 = fma2(u.x, w2[2 * i + 2], a2);
            a3 = fma2(u.y, w2[2 * i + 3], a3);
        }
        unsigned long long s = add2(add2(a0, a1), add2(a2, a3));
        float s0, s1;
        upk2(s, s0, s1);

        float h0 = ftanh(s0);
        float h1 = ftanh(s1);

        int nb = buf ^ 1;
        *(float2*)&hsh[nb][p][c][0] = make_float2(h0, h1);
        __syncthreads();
        buf = nb;
    }

    // Final projection: p = h_final @ Wph + bp  (h_final lives in hsh[buf])
    if (tid < ROWS * NC){
        int r = tid / NC;
        int k = tid % NC;
        float acc = bp[k];
#pragma unroll
        for (int j = 0; j < H; j++)
            acc += hsh[buf][r >> 1][j][r & 1] * __ldg(Wph + j * NC + k);
        out[(size_t)(rowBase + r) * NC + k] = acc;
    }
}

extern "C" void kernel_launch(void* const* d_in, const int* in_sizes, int n_in,
                              void* d_out, int out_size) {
    const float* x   = (const float*)d_in[0];
    const float* Whx = (const float*)d_in[1];
    const float* Whh = (const float*)d_in[2];
    const float* Wph = (const float*)d_in[3];
    const float* bh  = (const float*)d_in[4];
    const float* bp  = (const float*)d_in[5];
    float* out = (float*)d_out;

    rnn_kernel<<<4096 / ROWS, NTHREADS>>>(x, Whx, Whh, Wph, bh, bp, out);
}